// round 13
// baseline (speedup 1.0000x reference)
#include <cuda_runtime.h>
#include <cuda_bf16.h>
#include <math.h>

#define EMB 128
#define NHEAD 8
#define DHEAD 16
#define KNBR 32
#define NMAX 2048

typedef unsigned long long u64;

// Scratch (no cudaMalloc allowed)
__device__ float g_qkv[NMAX * 3 * EMB];
__device__ int   g_nbr[NMAX * KNBR];
__device__ float g_o  [NMAX * EMB];

__device__ __forceinline__ float dot4(float4 a, float4 b) {
    return a.x*b.x + a.y*b.y + a.z*b.z + a.w*b.w;
}
__device__ __forceinline__ u64 ffma2(u64 a, u64 b, u64 c) {
    u64 d;
    asm("fma.rn.f32x2 %0, %1, %2, %3;" : "=l"(d) : "l"(a), "l"(b), "l"(c));
    return d;
}
__device__ __forceinline__ float f2sum(u64 v) {
    return __uint_as_float((unsigned)v) + __uint_as_float((unsigned)(v >> 32));
}

// distance key of node j vs centroid (c0x,c0y,c0z); pad -> 0xFFFFFFFF
__device__ __forceinline__ unsigned dist_key(
    const float* __restrict__ coords9, int j, int n,
    float c0x, float c0y, float c0z)
{
    if (j >= n) return 0xFFFFFFFFu;
    const float inv3 = 1.0f / 3.0f;
    float a0 = coords9[j*9+0], a1 = coords9[j*9+1], a2 = coords9[j*9+2];
    float a3 = coords9[j*9+3], a4 = coords9[j*9+4], a5 = coords9[j*9+5];
    float a6 = coords9[j*9+6], a7 = coords9[j*9+7], a8 = coords9[j*9+8];
    float cx = (a0 + a3 + a6) * inv3;
    float cy = (a1 + a4 + a7) * inv3;
    float cz = (a2 + a5 + a8) * inv3;
    float dx = cx - c0x, dy = cy - c0y, dz = cz - c0z;
    return __float_as_uint(dx*dx + dy*dy + dz*dz);
}

// ---------------------------------------------------------------------------
// FAT kernel: heterogeneous blocks in ONE launch.
//   blocks [0, nqkv)        : QKV GEMM with fused input prep (32r x 96c, f32x2)
//   blocks [nqkv, nqkv + n) : exact top-32 radix selection for one node
// Selection is independent of the GEMM (keys come from coords9 directly), so
// the two block types fill each other's latency slots on the same SMs.
// ---------------------------------------------------------------------------
__global__ __launch_bounds__(256, 2) void fat_kernel(
    const float* __restrict__ x, const float* __restrict__ coords9,
    const float* __restrict__ prompt,
    const float* __restrict__ pe_w, const float* __restrict__ pe_b,
    const float* __restrict__ pe_g, const float* __restrict__ pe_bt,
    const float* __restrict__ W, const float* __restrict__ bias,
    int n, int nqkv)
{
    extern __shared__ float smem[];
    int tid  = threadIdx.x;
    int w    = tid >> 5;
    int lane = tid & 31;

    if ((int)blockIdx.x < nqkv) {
        // =================== QKV GEMM role (proven R9 code) ===============
        float* As = smem;                 // 32*128
        float* Ws = smem + 32*128;        // 96*132 (padded rows)

        int b    = blockIdx.x;
        int row0 = (b >> 2) * 32;
        int col0 = (b & 3) * 96;

        #pragma unroll
        for (int u = 0; u < 12; u++) {
            int lin = tid + u*256;
            int cc = lin >> 5, k4 = lin & 31;
            float4 wv = ((const float4*)(W + (size_t)(col0 + cc)*128))[k4];
            ((float4*)(Ws + cc*132))[k4] = wv;
        }

        #pragma unroll 1
        for (int u = 0; u < 4; u++) {
            int r = w*4 + u;
            int i = row0 + r;
            if (i >= n) {
                As[r*128 + lane] = 0.f; As[r*128 + 32 + lane] = 0.f;
                As[r*128 + 64 + lane] = 0.f; As[r*128 + 96 + lane] = 0.f;
                continue;
            }
            float cv = (lane < 9) ? coords9[i*9 + lane] : 0.f;
            const float inv3 = 1.0f / 3.0f;
            float cx = (__shfl_sync(0xffffffffu, cv, 0) + __shfl_sync(0xffffffffu, cv, 3) + __shfl_sync(0xffffffffu, cv, 6)) * inv3;
            float cy = (__shfl_sync(0xffffffffu, cv, 1) + __shfl_sync(0xffffffffu, cv, 4) + __shfl_sync(0xffffffffu, cv, 7)) * inv3;
            float cz = (__shfl_sync(0xffffffffu, cv, 2) + __shfl_sync(0xffffffffu, cv, 5) + __shfl_sync(0xffffffffu, cv, 8)) * inv3;

            float v = cx*pe_w[lane] + cy*pe_w[32+lane] + cz*pe_w[64+lane] + pe_b[lane];
            float h = 0.5f * v * (1.0f + erff(v * 0.70710678118654752f));

            float s = h, s2 = h*h;
            #pragma unroll
            for (int off = 16; off; off >>= 1) {
                s  += __shfl_xor_sync(0xffffffffu, s,  off);
                s2 += __shfl_xor_sync(0xffffffffu, s2, off);
            }
            float mu  = s * (1.0f/32.0f);
            float var = s2 * (1.0f/32.0f) - mu*mu;
            float inv = rsqrtf(var + 1e-5f);

            As[r*128 +      lane] = x[i*EMB +      lane] + prompt[     lane];
            As[r*128 + 32 + lane] = x[i*EMB + 32 + lane] + prompt[32 + lane];
            As[r*128 + 64 + lane] = x[i*EMB + 64 + lane] + prompt[64 + lane];
            As[r*128 + 96 + lane] = (h - mu) * inv * pe_g[lane] + pe_bt[lane];
        }
        __syncthreads();

        int tx = tid & 31;
        int ty = tid >> 5;
        const ulonglong2* wp[3];
        #pragma unroll
        for (int c = 0; c < 3; c++) wp[c] = (const ulonglong2*)(Ws + (tx + 32*c)*132);
        const ulonglong2* ap[4];
        #pragma unroll
        for (int r = 0; r < 4; r++) ap[r] = (const ulonglong2*)(As + (ty*4 + r)*128);

        u64 acc[4][3];
        #pragma unroll
        for (int r = 0; r < 4; r++)
            #pragma unroll
            for (int c = 0; c < 3; c++) acc[r][c] = 0ULL;

        #pragma unroll 4
        for (int k4 = 0; k4 < 32; k4++) {
            ulonglong2 wv[3], av[4];
            #pragma unroll
            for (int c = 0; c < 3; c++) wv[c] = wp[c][k4];
            #pragma unroll
            for (int r = 0; r < 4; r++) av[r] = ap[r][k4];
            #pragma unroll
            for (int r = 0; r < 4; r++)
                #pragma unroll
                for (int c = 0; c < 3; c++) {
                    acc[r][c] = ffma2(av[r].x, wv[c].x, acc[r][c]);
                    acc[r][c] = ffma2(av[r].y, wv[c].y, acc[r][c]);
                }
        }

        float bv[3];
        #pragma unroll
        for (int c = 0; c < 3; c++) bv[c] = bias[col0 + tx + 32*c];
        #pragma unroll
        for (int r = 0; r < 4; r++) {
            int gr = row0 + ty*4 + r;
            if (gr < n) {
                #pragma unroll
                for (int c = 0; c < 3; c++)
                    g_qkv[(size_t)gr*384 + col0 + tx + 32*c] = f2sum(acc[r][c]) + bv[c];
            }
        }
    } else {
        // =================== SELECTION role (proven R9 radix) =============
        __shared__ unsigned s_hist[256];
        __shared__ int      s_tie[64];
        __shared__ unsigned s_Tkey, s_rem;
        __shared__ int      s_cnt, s_tcnt;

        int i = (int)blockIdx.x - nqkv;

        s_hist[tid] = 0u;
        if (tid == 0) { s_Tkey = 0u; s_rem = KNBR; s_cnt = 0; s_tcnt = 0; }
        __syncthreads();

        // own centroid: all threads compute identically (broadcast loads)
        const float inv3 = 1.0f / 3.0f;
        float c0x, c0y, c0z;
        {
            float a0 = coords9[i*9+0], a1 = coords9[i*9+1], a2 = coords9[i*9+2];
            float a3 = coords9[i*9+3], a4 = coords9[i*9+4], a5 = coords9[i*9+5];
            float a6 = coords9[i*9+6], a7 = coords9[i*9+7], a8 = coords9[i*9+8];
            c0x = (a0 + a3 + a6) * inv3;
            c0y = (a1 + a4 + a7) * inv3;
            c0z = (a2 + a5 + a8) * inv3;
        }

        // gen pass: keys in registers + warp-aggregated level-0 histogram
        unsigned kreg[NMAX/256];
        #pragma unroll
        for (int u = 0; u < NMAX/256; u++) {
            int j = tid + u*256;
            unsigned k = dist_key(coords9, j, n, c0x, c0y, c0z);
            kreg[u] = k;
            int bb = k >> 24;
            unsigned grp = __match_any_sync(0xffffffffu, bb);
            if ((grp & ((1u << lane) - 1u)) == 0u)
                atomicAdd(&s_hist[bb], (unsigned)__popc(grp));
        }
        __syncthreads();

        // radix descent: 4 levels of 8 bits
        #pragma unroll 1
        for (int level = 0; level < 4; level++) {
            int shift = 24 - level*8;

            if (tid < 32) {
                unsigned h[8]; unsigned lsum = 0u;
                #pragma unroll
                for (int u = 0; u < 8; u++) { h[u] = s_hist[lane*8 + u]; lsum += h[u]; }
                unsigned incl = lsum;
                #pragma unroll
                for (int off = 1; off < 32; off <<= 1) {
                    unsigned v = __shfl_up_sync(0xffffffffu, incl, off);
                    if (lane >= off) incl += v;
                }
                unsigned cum = incl - lsum;
                unsigned rem = s_rem;
                int bloc = -1; unsigned cb_loc = 0u;
                #pragma unroll
                for (int u = 0; u < 8; u++) {
                    if (cum < rem && cum + h[u] >= rem) { bloc = lane*8 + u; cb_loc = cum; }
                    cum += h[u];
                }
                unsigned bal = __ballot_sync(0xffffffffu, bloc >= 0);
                int src = __ffs(bal) - 1;
                if (lane == src) {
                    s_Tkey |= ((unsigned)bloc) << shift;
                    s_rem   = rem - cb_loc;
                }
            }
            __syncthreads();

            if (level < 3) {
                unsigned pref = s_Tkey >> shift;
                s_hist[tid] = 0u;
                __syncthreads();
                #pragma unroll
                for (int u = 0; u < NMAX/256; u++) {
                    unsigned k = kreg[u];
                    if ((k >> shift) == pref)
                        atomicAdd(&s_hist[(k >> (shift - 8)) & 0xFFu], 1u);
                }
                __syncthreads();
            }
        }

        // emission: keys < T direct to g_nbr; keys == T into tie buffer
        unsigned T = s_Tkey;
        int need = (int)s_rem;
        int out_base = i * KNBR;
        #pragma unroll
        for (int u = 0; u < NMAX/256; u++) {
            unsigned k = kreg[u];
            if (k < T) {
                int p = atomicAdd(&s_cnt, 1);
                g_nbr[out_base + p] = tid + u*256;
            } else if (k == T) {
                int p = atomicAdd(&s_tcnt, 1);
                if (p < 64) s_tie[p] = tid + u*256;
            }
        }
        __syncthreads();

        if (tid < 32) {
            int base = s_cnt;
            int t = s_tcnt;
            if (t <= 64) {
                // select `need` smallest tie indices (typically t=need=1)
                int v0 = (lane < t)      ? s_tie[lane]      : 0x7fffffff;
                int v1 = (lane + 32 < t) ? s_tie[lane + 32] : 0x7fffffff;
                #pragma unroll 1
                for (int it = 0; it < need; it++) {
                    int mn = min(v0, v1);
                    #pragma unroll
                    for (int off = 16; off; off >>= 1)
                        mn = min(mn, __shfl_xor_sync(0xffffffffu, mn, off));
                    if (v0 == mn) v0 = 0x7fffffff;
                    else if (v1 == mn) v1 = 0x7fffffff;
                    if (lane == 0) g_nbr[out_base + base + it] = mn;
                }
            } else {
                // degenerate fallback: ordered ballot scan, keys recomputed
                int need2 = need; int pos = base;
                #pragma unroll 1
                for (int u = 0; u < NMAX/32 && need2 > 0; u++) {
                    int j = u*32 + lane;
                    unsigned k = dist_key(coords9, j, n, c0x, c0y, c0z);
                    unsigned beq = __ballot_sync(0xffffffffu, k == T);
                    if (beq) {
                        int neq  = __popc(beq);
                        int take = need2 < neq ? need2 : neq;
                        if (k == T) {
                            int rank = __popc(beq & ((1u << lane) - 1u));
                            if (rank < take) g_nbr[out_base + pos + rank] = j;
                        }
                        pos  += take;
                        need2 -= take;
                    }
                }
            }
        }
    }
}

// ---------------------------------------------------------------------------
// Attention only (selection already done): one block (256 threads) per node.
// Head-per-warp scores + softmax, register V, deterministic partial reduce.
// ---------------------------------------------------------------------------
__global__ __launch_bounds__(256) void attn_lite_kernel(int n)
{
    __shared__ float s_p[NHEAD][KNBR];       // 1 KB
    __shared__ float s_part[NHEAD][EMB];     // 4 KB

    int i    = blockIdx.x;
    int tid  = threadIdx.x;
    int w    = tid >> 5;
    int lane = tid & 31;

    int idx_l = g_nbr[i*KNBR + lane];
    int vrow[4];
    #pragma unroll
    for (int u = 0; u < 4; u++) vrow[u] = __shfl_sync(0xffffffffu, idx_l, w*4 + u);

    // prefetch V rows (warp w owns neighbors 4w..4w+3)
    float4 vreg[4];
    #pragma unroll
    for (int u = 0; u < 4; u++)
        vreg[u] = ((const float4*)(g_qkv + (size_t)vrow[u]*384 + 256))[lane];

    // scores: head h = w, lane = neighbor
    {
        const float4* kp = (const float4*)(g_qkv + (size_t)idx_l*384 + 128 + w*DHEAD);
        const float4* qp = (const float4*)(g_qkv + (size_t)i*384 + w*DHEAD);
        float4 q0 = qp[0], q1 = qp[1], q2 = qp[2], q3 = qp[3];
        float4 k0 = kp[0], k1 = kp[1], k2 = kp[2], k3 = kp[3];
        float s = dot4(q0,k0) + dot4(q1,k1) + dot4(q2,k2) + dot4(q3,k3);
        s *= 0.25f;   // 1/sqrt(16)

        float m = s;
        #pragma unroll
        for (int off = 16; off; off >>= 1)
            m = fmaxf(m, __shfl_xor_sync(0xffffffffu, m, off));
        float p = expf(s - m);
        float den = p;
        #pragma unroll
        for (int off = 16; off; off >>= 1)
            den += __shfl_xor_sync(0xffffffffu, den, off);
        s_p[w][lane] = p / den;
    }
    __syncthreads();

    {
        int hh = lane >> 2;
        float4 acc = make_float4(0.f,0.f,0.f,0.f);
        #pragma unroll
        for (int u = 0; u < 4; u++) {
            float p = s_p[hh][w*4 + u];
            acc.x += p * vreg[u].x;
            acc.y += p * vreg[u].y;
            acc.z += p * vreg[u].z;
            acc.w += p * vreg[u].w;
        }
        ((float4*)s_part[w])[lane] = acc;
    }
    __syncthreads();

    if (tid < 128) {
        float o = 0.f;
        #pragma unroll
        for (int ww = 0; ww < NHEAD; ww++) o += s_part[ww][tid];
        g_o[(size_t)i*EMB + tid] = o;
    }
}

// ---------------------------------------------------------------------------
// Output GEMM (proven R9): 32 rows x 64 cols, 256 threads, 4x2 tile, float4.
// Grid (2,63)=126 -> single wave. With sanitize.
// ---------------------------------------------------------------------------
__global__ __launch_bounds__(256) void out_gemm_kernel(
    const float* __restrict__ W, const float* __restrict__ bias,
    float* __restrict__ C, int n)
{
    extern __shared__ float smem[];
    float* As = smem;                 // 32*128
    float* Ws = smem + 32*128;        // 64*132

    int row0 = blockIdx.y * 32;
    int col0 = blockIdx.x * 64;
    int tid  = threadIdx.x;

    #pragma unroll
    for (int u = 0; u < 8; u++) {
        int lin = tid + u*256;
        int cc = lin >> 5, k4 = lin & 31;
        float4 wv = ((const float4*)(W + (size_t)(col0 + cc)*128))[k4];
        ((float4*)(Ws + cc*132))[k4] = wv;
    }
    #pragma unroll
    for (int u = 0; u < 4; u++) {
        int lin = tid + u*256;
        int r = lin >> 5, c4 = lin & 31;
        int gr = row0 + r;
        float4 av = make_float4(0.f,0.f,0.f,0.f);
        if (gr < n) av = ((const float4*)(g_o + (size_t)gr*128))[c4];
        ((float4*)(As + r*128))[c4] = av;
    }
    __syncthreads();

    int tx = tid & 31;
    int ty = tid >> 5;
    const float4* w0p = (const float4*)(Ws + tx*132);
    const float4* w1p = (const float4*)(Ws + (tx+32)*132);

    float acc[4][2] = {{0.f,0.f},{0.f,0.f},{0.f,0.f},{0.f,0.f}};
    #pragma unroll
    for (int k4 = 0; k4 < 32; k4++) {
        float4 w0 = w0p[k4], w1 = w1p[k4];
        #pragma unroll
        for (int r = 0; r < 4; r++) {
            float4 a = ((const float4*)(As + (ty*4+r)*128))[k4];
            acc[r][0] += dot4(a, w0);
            acc[r][1] += dot4(a, w1);
        }
    }

    int c0 = col0 + tx, c1 = col0 + tx + 32;
    float b0 = bias[c0], b1 = bias[c1];
    #pragma unroll
    for (int r = 0; r < 4; r++) {
        int gr = row0 + ty*4 + r;
        if (gr < n) {
            float v0 = acc[r][0] + b0;
            float v1 = acc[r][1] + b1;
            if (isnan(v0)) v0 = 0.f;
            if (isnan(v1)) v1 = 0.f;
            v0 = fminf(fmaxf(v0, -1e4f), 1e4f);
            v1 = fminf(fmaxf(v1, -1e4f), 1e4f);
            C[(size_t)gr*EMB + c0] = v0;
            C[(size_t)gr*EMB + c1] = v1;
        }
    }
}

// ---------------------------------------------------------------------------
extern "C" void kernel_launch(void* const* d_in, const int* in_sizes, int n_in,
                              void* d_out, int out_size)
{
    const float* x       = (const float*)d_in[0];
    const float* coords9 = (const float*)d_in[1];
    const float* prompt  = (const float*)d_in[2];
    const float* pe_w    = (const float*)d_in[3];
    const float* pe_b    = (const float*)d_in[4];
    const float* pe_g    = (const float*)d_in[5];
    const float* pe_bt   = (const float*)d_in[6];
    const float* in_w    = (const float*)d_in[7];
    const float* in_b    = (const float*)d_in[8];
    const float* out_w   = (const float*)d_in[9];
    const float* out_b   = (const float*)d_in[10];
    float* out = (float*)d_out;

    int n = in_sizes[0] / EMB;     // 2000
    int nrb = (n + 31) / 32;       // 63
    int nqkv = 4 * nrb;            // 252 qkv blocks

    const int FAT_SMEM = (32*128 + 96*132) * (int)sizeof(float);    // 67072 B
    const int OUT_SMEM = (32*128 + 64*132) * (int)sizeof(float);    // 50176 B
    cudaFuncSetAttribute(fat_kernel, cudaFuncAttributeMaxDynamicSharedMemorySize, FAT_SMEM);
    cudaFuncSetAttribute(out_gemm_kernel, cudaFuncAttributeMaxDynamicSharedMemorySize, OUT_SMEM);

    fat_kernel<<<nqkv + n, 256, FAT_SMEM>>>(
        x, coords9, prompt, pe_w, pe_b, pe_g, pe_bt, in_w, in_b, n, nqkv);
    attn_lite_kernel<<<n, 256>>>(n);
    out_gemm_kernel<<<dim3(2, nrb), 256, OUT_SMEM>>>(out_w, out_b, out, n);
}

// round 14
// speedup vs baseline: 1.3666x; 1.3666x over previous
#include <cuda_runtime.h>
#include <cuda_bf16.h>
#include <math.h>

#define EMB 128
#define NHEAD 8
#define DHEAD 16
#define KNBR 32
#define NMAX 2048

typedef unsigned long long u64;

// Scratch (no cudaMalloc allowed)
__device__ float4 g_cent[NMAX];
__device__ float  g_qkv [NMAX * 3 * EMB];
__device__ float  g_o   [NMAX * EMB];

__device__ __forceinline__ float dot4(float4 a, float4 b) {
    return a.x*b.x + a.y*b.y + a.z*b.z + a.w*b.w;
}
__device__ __forceinline__ u64 ffma2(u64 a, u64 b, u64 c) {
    u64 d;
    asm("fma.rn.f32x2 %0, %1, %2, %3;" : "=l"(d) : "l"(a), "l"(b), "l"(c));
    return d;
}
__device__ __forceinline__ float f2sum(u64 v) {
    return __uint_as_float((unsigned)v) + __uint_as_float((unsigned)(v >> 32));
}

// ---------------------------------------------------------------------------
// QKV GEMM with fused input prep (proven R10): 32r x 96c, 256 threads, 4x3
// f32x2 tile, 67KB smem -> 2 blocks/SM, grid (4,63)=252 -> single wave.
// Col-block 0 also writes g_cent.
// ---------------------------------------------------------------------------
__global__ __launch_bounds__(256, 2) void qkv_gemm_kernel(
    const float* __restrict__ x, const float* __restrict__ coords9,
    const float* __restrict__ prompt,
    const float* __restrict__ pe_w, const float* __restrict__ pe_b,
    const float* __restrict__ pe_g, const float* __restrict__ pe_bt,
    const float* __restrict__ W, const float* __restrict__ bias, int n)
{
    extern __shared__ float smem[];
    float* As = smem;                 // 32*128
    float* Ws = smem + 32*128;        // 96*132 (padded rows)

    int row0 = blockIdx.y * 32;
    int col0 = blockIdx.x * 96;
    int tid  = threadIdx.x;
    int w    = tid >> 5;
    int lane = tid & 31;

    #pragma unroll
    for (int u = 0; u < 12; u++) {
        int lin = tid + u*256;
        int cc = lin >> 5, k4 = lin & 31;
        float4 wv = ((const float4*)(W + (size_t)(col0 + cc)*128))[k4];
        ((float4*)(Ws + cc*132))[k4] = wv;
    }

    #pragma unroll 1
    for (int u = 0; u < 4; u++) {
        int r = w*4 + u;
        int i = row0 + r;
        if (i >= n) {
            As[r*128 + lane] = 0.f; As[r*128 + 32 + lane] = 0.f;
            As[r*128 + 64 + lane] = 0.f; As[r*128 + 96 + lane] = 0.f;
            continue;
        }
        float cv = (lane < 9) ? coords9[i*9 + lane] : 0.f;
        const float inv3 = 1.0f / 3.0f;
        float cx = (__shfl_sync(0xffffffffu, cv, 0) + __shfl_sync(0xffffffffu, cv, 3) + __shfl_sync(0xffffffffu, cv, 6)) * inv3;
        float cy = (__shfl_sync(0xffffffffu, cv, 1) + __shfl_sync(0xffffffffu, cv, 4) + __shfl_sync(0xffffffffu, cv, 7)) * inv3;
        float cz = (__shfl_sync(0xffffffffu, cv, 2) + __shfl_sync(0xffffffffu, cv, 5) + __shfl_sync(0xffffffffu, cv, 8)) * inv3;
        if (col0 == 0 && lane == 0) g_cent[i] = make_float4(cx, cy, cz, 0.f);

        float v = cx*pe_w[lane] + cy*pe_w[32+lane] + cz*pe_w[64+lane] + pe_b[lane];
        float h = 0.5f * v * (1.0f + erff(v * 0.70710678118654752f));

        float s = h, s2 = h*h;
        #pragma unroll
        for (int off = 16; off; off >>= 1) {
            s  += __shfl_xor_sync(0xffffffffu, s,  off);
            s2 += __shfl_xor_sync(0xffffffffu, s2, off);
        }
        float mu  = s * (1.0f/32.0f);
        float var = s2 * (1.0f/32.0f) - mu*mu;
        float inv = rsqrtf(var + 1e-5f);

        As[r*128 +      lane] = x[i*EMB +      lane] + prompt[     lane];
        As[r*128 + 32 + lane] = x[i*EMB + 32 + lane] + prompt[32 + lane];
        As[r*128 + 64 + lane] = x[i*EMB + 64 + lane] + prompt[64 + lane];
        As[r*128 + 96 + lane] = (h - mu) * inv * pe_g[lane] + pe_bt[lane];
    }
    __syncthreads();

    int tx = tid & 31;
    int ty = tid >> 5;
    const ulonglong2* wp[3];
    #pragma unroll
    for (int c = 0; c < 3; c++) wp[c] = (const ulonglong2*)(Ws + (tx + 32*c)*132);
    const ulonglong2* ap[4];
    #pragma unroll
    for (int r = 0; r < 4; r++) ap[r] = (const ulonglong2*)(As + (ty*4 + r)*128);

    u64 acc[4][3];
    #pragma unroll
    for (int r = 0; r < 4; r++)
        #pragma unroll
        for (int c = 0; c < 3; c++) acc[r][c] = 0ULL;

    #pragma unroll 4
    for (int k4 = 0; k4 < 32; k4++) {
        ulonglong2 wv[3], av[4];
        #pragma unroll
        for (int c = 0; c < 3; c++) wv[c] = wp[c][k4];
        #pragma unroll
        for (int r = 0; r < 4; r++) av[r] = ap[r][k4];
        #pragma unroll
        for (int r = 0; r < 4; r++)
            #pragma unroll
            for (int c = 0; c < 3; c++) {
                acc[r][c] = ffma2(av[r].x, wv[c].x, acc[r][c]);
                acc[r][c] = ffma2(av[r].y, wv[c].y, acc[r][c]);
            }
    }

    float bv[3];
    #pragma unroll
    for (int c = 0; c < 3; c++) bv[c] = bias[col0 + tx + 32*c];
    #pragma unroll
    for (int r = 0; r < 4; r++) {
        int gr = row0 + ty*4 + r;
        if (gr < n) {
            #pragma unroll
            for (int c = 0; c < 3; c++)
                g_qkv[(size_t)gr*384 + col0 + tx + 32*c] = f2sum(acc[r][c]) + bv[c];
        }
    }
}

// ---------------------------------------------------------------------------
// Fused top-K + attention, TWO queries per block (nodes 2b, 2b+1).
// One g_cent sweep feeds both queries' keys; radix descent runs the two
// queries on warps 0/1 in parallel; attention loops q=0,1 with the proven
// R9 code. Ties at rank-32 take lowest indices (matches jax); set order
// irrelevant. Grid = ceil(n/2) = 1000 -> ~1 wave at ~8KB smem.
// ---------------------------------------------------------------------------
__global__ __launch_bounds__(256) void fused_attn_kernel(int n)
{
    __shared__ unsigned s_hist[2][256];       // 2 KB
    __shared__ float    s_p[NHEAD][KNBR];     // 1 KB
    __shared__ float    s_part[NHEAD][EMB];   // 4 KB
    __shared__ int      s_nbr[2][KNBR];
    __shared__ int      s_tie[2][64];
    __shared__ unsigned s_Tkey[2], s_rem[2];
    __shared__ int      s_cnt[2], s_tcnt[2];

    int tid  = threadIdx.x;
    int w    = tid >> 5;
    int lane = tid & 31;

    int i0 = blockIdx.x * 2;
    int q1ok = (i0 + 1 < n);
    int i1 = q1ok ? i0 + 1 : i0;     // duplicate query if odd tail (writes guarded)

    s_hist[0][tid & 255] = 0u;       // tid<256: covers [0][0..255]
    s_hist[1][tid & 255] = 0u;
    if (tid < 2) { s_Tkey[tid] = 0u; s_rem[tid] = KNBR; s_cnt[tid] = 0; s_tcnt[tid] = 0; }
    __syncthreads();

    float4 c0 = g_cent[i0];
    float4 c1 = g_cent[i1];

    // ---- gen pass: one centroid sweep, two key sets ----------------------
    unsigned kreg0[NMAX/256], kreg1[NMAX/256];
    #pragma unroll
    for (int u = 0; u < NMAX/256; u++) {
        int j = tid + u*256;
        unsigned k0 = 0xFFFFFFFFu, k1 = 0xFFFFFFFFu;   // pad bin 255
        if (j < n) {
            float4 cj = g_cent[j];
            float dx0 = cj.x - c0.x, dy0 = cj.y - c0.y, dz0 = cj.z - c0.z;
            float dx1 = cj.x - c1.x, dy1 = cj.y - c1.y, dz1 = cj.z - c1.z;
            k0 = __float_as_uint(dx0*dx0 + dy0*dy0 + dz0*dz0);
            k1 = __float_as_uint(dx1*dx1 + dy1*dy1 + dz1*dz1);
        }
        kreg0[u] = k0; kreg1[u] = k1;
        int b0 = k0 >> 24;
        unsigned g0 = __match_any_sync(0xffffffffu, b0);
        if ((g0 & ((1u << lane) - 1u)) == 0u)
            atomicAdd(&s_hist[0][b0], (unsigned)__popc(g0));
        int b1 = k1 >> 24;
        unsigned g1 = __match_any_sync(0xffffffffu, b1);
        if ((g1 & ((1u << lane) - 1u)) == 0u)
            atomicAdd(&s_hist[1][b1], (unsigned)__popc(g1));
    }
    __syncthreads();

    // ---- radix descent: warps 0/1 scan their query's bins in parallel ----
    #pragma unroll 1
    for (int level = 0; level < 4; level++) {
        int shift = 24 - level*8;

        if (w < 2) {
            int q = w;
            unsigned h[8]; unsigned lsum = 0u;
            #pragma unroll
            for (int u = 0; u < 8; u++) { h[u] = s_hist[q][lane*8 + u]; lsum += h[u]; }
            unsigned incl = lsum;
            #pragma unroll
            for (int off = 1; off < 32; off <<= 1) {
                unsigned v = __shfl_up_sync(0xffffffffu, incl, off);
                if (lane >= off) incl += v;
            }
            unsigned cum = incl - lsum;
            unsigned rem = s_rem[q];
            int bloc = -1; unsigned cb_loc = 0u;
            #pragma unroll
            for (int u = 0; u < 8; u++) {
                if (cum < rem && cum + h[u] >= rem) { bloc = lane*8 + u; cb_loc = cum; }
                cum += h[u];
            }
            unsigned bal = __ballot_sync(0xffffffffu, bloc >= 0);
            int src = __ffs(bal) - 1;
            if (lane == src) {
                s_Tkey[q] |= ((unsigned)bloc) << shift;
                s_rem[q]   = rem - cb_loc;
            }
        }
        __syncthreads();

        if (level < 3) {
            unsigned p0 = s_Tkey[0] >> shift;
            unsigned p1 = s_Tkey[1] >> shift;
            s_hist[0][tid & 255] = 0u;
            s_hist[1][tid & 255] = 0u;
            __syncthreads();
            #pragma unroll
            for (int u = 0; u < NMAX/256; u++) {
                unsigned k0 = kreg0[u];
                if ((k0 >> shift) == p0)
                    atomicAdd(&s_hist[0][(k0 >> (shift - 8)) & 0xFFu], 1u);
                unsigned k1 = kreg1[u];
                if ((k1 >> shift) == p1)
                    atomicAdd(&s_hist[1][(k1 >> (shift - 8)) & 0xFFu], 1u);
            }
            __syncthreads();
        }
    }

    // ---- emission for both queries ---------------------------------------
    unsigned T0 = s_Tkey[0], T1 = s_Tkey[1];
    #pragma unroll
    for (int u = 0; u < NMAX/256; u++) {
        int j = tid + u*256;
        unsigned k0 = kreg0[u];
        if (k0 < T0) {
            int p = atomicAdd(&s_cnt[0], 1);
            s_nbr[0][p] = j;
        } else if (k0 == T0) {
            int p = atomicAdd(&s_tcnt[0], 1);
            if (p < 64) s_tie[0][p] = j;
        }
        unsigned k1 = kreg1[u];
        if (k1 < T1) {
            int p = atomicAdd(&s_cnt[1], 1);
            s_nbr[1][p] = j;
        } else if (k1 == T1) {
            int p = atomicAdd(&s_tcnt[1], 1);
            if (p < 64) s_tie[1][p] = j;
        }
    }
    __syncthreads();

    // ---- tie resolution: warp q handles query q --------------------------
    if (w < 2) {
        int q = w;
        unsigned Tq = (q == 0) ? T0 : T1;
        float4 cq = (q == 0) ? c0 : c1;
        int base = s_cnt[q];
        int t    = s_tcnt[q];
        int need = (int)s_rem[q];
        if (t <= 64) {
            int v0 = (lane < t)      ? s_tie[q][lane]      : 0x7fffffff;
            int v1 = (lane + 32 < t) ? s_tie[q][lane + 32] : 0x7fffffff;
            #pragma unroll 1
            for (int it = 0; it < need; it++) {
                int mn = min(v0, v1);
                #pragma unroll
                for (int off = 16; off; off >>= 1)
                    mn = min(mn, __shfl_xor_sync(0xffffffffu, mn, off));
                if (v0 == mn) v0 = 0x7fffffff;
                else if (v1 == mn) v1 = 0x7fffffff;
                if (lane == 0) s_nbr[q][base + it] = mn;
            }
        } else {
            // degenerate fallback: ordered ballot scan, keys recomputed
            int need2 = need; int pos = base;
            #pragma unroll 1
            for (int u = 0; u < NMAX/32 && need2 > 0; u++) {
                int j = u*32 + lane;
                unsigned k = 0xFFFFFFFFu;
                if (j < n) {
                    float4 cj = g_cent[j];
                    float dx = cj.x - cq.x, dy = cj.y - cq.y, dz = cj.z - cq.z;
                    k = __float_as_uint(dx*dx + dy*dy + dz*dz);
                }
                unsigned beq = __ballot_sync(0xffffffffu, k == Tq);
                if (beq) {
                    int neq  = __popc(beq);
                    int take = need2 < neq ? need2 : neq;
                    if (k == Tq) {
                        int rank = __popc(beq & ((1u << lane) - 1u));
                        if (rank < take) s_nbr[q][pos + rank] = j;
                    }
                    pos  += take;
                    need2 -= take;
                }
            }
        }
    }
    __syncthreads();

    // ---- attention: q = 0, 1 sequentially (uniform control flow) ---------
    int nq = q1ok ? 2 : 1;
    #pragma unroll 1
    for (int q = 0; q < nq; q++) {
        int i = i0 + q;

        int idx_l = s_nbr[q][lane];
        int vrow[4];
        #pragma unroll
        for (int u = 0; u < 4; u++) vrow[u] = s_nbr[q][w*4 + u];

        float4 vreg[4];
        #pragma unroll
        for (int u = 0; u < 4; u++)
            vreg[u] = ((const float4*)(g_qkv + (size_t)vrow[u]*384 + 256))[lane];

        {
            const float4* kp = (const float4*)(g_qkv + (size_t)idx_l*384 + 128 + w*DHEAD);
            const float4* qp = (const float4*)(g_qkv + (size_t)i*384 + w*DHEAD);
            float4 q0v = qp[0], q1v = qp[1], q2v = qp[2], q3v = qp[3];
            float4 k0v = kp[0], k1v = kp[1], k2v = kp[2], k3v = kp[3];
            float s = dot4(q0v,k0v) + dot4(q1v,k1v) + dot4(q2v,k2v) + dot4(q3v,k3v);
            s *= 0.25f;   // 1/sqrt(16)

            float m = s;
            #pragma unroll
            for (int off = 16; off; off >>= 1)
                m = fmaxf(m, __shfl_xor_sync(0xffffffffu, m, off));
            float p = expf(s - m);
            float den = p;
            #pragma unroll
            for (int off = 16; off; off >>= 1)
                den += __shfl_xor_sync(0xffffffffu, den, off);
            s_p[w][lane] = p / den;
        }
        __syncthreads();

        {
            int hh = lane >> 2;
            float4 acc = make_float4(0.f,0.f,0.f,0.f);
            #pragma unroll
            for (int u = 0; u < 4; u++) {
                float p = s_p[hh][w*4 + u];
                acc.x += p * vreg[u].x;
                acc.y += p * vreg[u].y;
                acc.z += p * vreg[u].z;
                acc.w += p * vreg[u].w;
            }
            ((float4*)s_part[w])[lane] = acc;
        }
        __syncthreads();

        if (tid < 128) {
            float o = 0.f;
            #pragma unroll
            for (int ww = 0; ww < NHEAD; ww++) o += s_part[ww][tid];
            g_o[(size_t)i*EMB + tid] = o;
        }
        __syncthreads();
    }
}

// ---------------------------------------------------------------------------
// Output GEMM (proven): 32 rows x 64 cols, 256 threads, 4x2 tile, float4.
// Grid (2,63)=126 -> single wave. With sanitize.
// ---------------------------------------------------------------------------
__global__ __launch_bounds__(256) void out_gemm_kernel(
    const float* __restrict__ W, const float* __restrict__ bias,
    float* __restrict__ C, int n)
{
    extern __shared__ float smem[];
    float* As = smem;                 // 32*128
    float* Ws = smem + 32*128;        // 64*132

    int row0 = blockIdx.y * 32;
    int col0 = blockIdx.x * 64;
    int tid  = threadIdx.x;

    #pragma unroll
    for (int u = 0; u < 8; u++) {
        int lin = tid + u*256;
        int cc = lin >> 5, k4 = lin & 31;
        float4 wv = ((const float4*)(W + (size_t)(col0 + cc)*128))[k4];
        ((float4*)(Ws + cc*132))[k4] = wv;
    }
    #pragma unroll
    for (int u = 0; u < 4; u++) {
        int lin = tid + u*256;
        int r = lin >> 5, c4 = lin & 31;
        int gr = row0 + r;
        float4 av = make_float4(0.f,0.f,0.f,0.f);
        if (gr < n) av = ((const float4*)(g_o + (size_t)gr*128))[c4];
        ((float4*)(As + r*128))[c4] = av;
    }
    __syncthreads();

    int tx = tid & 31;
    int ty = tid >> 5;
    const float4* w0p = (const float4*)(Ws + tx*132);
    const float4* w1p = (const float4*)(Ws + (tx+32)*132);

    float acc[4][2] = {{0.f,0.f},{0.f,0.f},{0.f,0.f},{0.f,0.f}};
    #pragma unroll
    for (int k4 = 0; k4 < 32; k4++) {
        float4 w0 = w0p[k4], w1 = w1p[k4];
        #pragma unroll
        for (int r = 0; r < 4; r++) {
            float4 a = ((const float4*)(As + (ty*4+r)*128))[k4];
            acc[r][0] += dot4(a, w0);
            acc[r][1] += dot4(a, w1);
        }
    }

    int c0 = col0 + tx, c1 = col0 + tx + 32;
    float b0 = bias[c0], b1 = bias[c1];
    #pragma unroll
    for (int r = 0; r < 4; r++) {
        int gr = row0 + ty*4 + r;
        if (gr < n) {
            float v0 = acc[r][0] + b0;
            float v1 = acc[r][1] + b1;
            if (isnan(v0)) v0 = 0.f;
            if (isnan(v1)) v1 = 0.f;
            v0 = fminf(fmaxf(v0, -1e4f), 1e4f);
            v1 = fminf(fmaxf(v1, -1e4f), 1e4f);
            C[(size_t)gr*EMB + c0] = v0;
            C[(size_t)gr*EMB + c1] = v1;
        }
    }
}

// ---------------------------------------------------------------------------
extern "C" void kernel_launch(void* const* d_in, const int* in_sizes, int n_in,
                              void* d_out, int out_size)
{
    const float* x       = (const float*)d_in[0];
    const float* coords9 = (const float*)d_in[1];
    const float* prompt  = (const float*)d_in[2];
    const float* pe_w    = (const float*)d_in[3];
    const float* pe_b    = (const float*)d_in[4];
    const float* pe_g    = (const float*)d_in[5];
    const float* pe_bt   = (const float*)d_in[6];
    const float* in_w    = (const float*)d_in[7];
    const float* in_b    = (const float*)d_in[8];
    const float* out_w   = (const float*)d_in[9];
    const float* out_b   = (const float*)d_in[10];
    float* out = (float*)d_out;

    int n = in_sizes[0] / EMB;     // 2000
    int nrb = (n + 31) / 32;       // 63

    const int QKV_SMEM = (32*128 + 96*132) * (int)sizeof(float);    // 67072 B
    const int OUT_SMEM = (32*128 + 64*132) * (int)sizeof(float);    // 50176 B
    cudaFuncSetAttribute(qkv_gemm_kernel, cudaFuncAttributeMaxDynamicSharedMemorySize, QKV_SMEM);
    cudaFuncSetAttribute(out_gemm_kernel, cudaFuncAttributeMaxDynamicSharedMemorySize, OUT_SMEM);

    qkv_gemm_kernel<<<dim3(4, nrb), 256, QKV_SMEM>>>(
        x, coords9, prompt, pe_w, pe_b, pe_g, pe_bt, in_w, in_b, n);
    fused_attn_kernel<<<(n + 1) / 2, 256>>>(n);
    out_gemm_kernel<<<dim3(2, nrb), 256, OUT_SMEM>>>(out_w, out_b, out, n);
}